// round 1
// baseline (speedup 1.0000x reference)
#include <cuda_runtime.h>
#include <math.h>

#define D_      256
#define DA_     128
#define BSZ_    256
#define MAXLEN_ 1024

// Scratch: v[b][j] = sum_a tanh(trans_q[b,j,a] + b_f[j,a]) * w_h[a]
__device__ float g_v[BSZ_ * D_];

// ---------------------------------------------------------------------------
// Kernel 1: fused GEMM + tanh + weighted reduce over a.
// C[b, (j,a)] = sum_k emb_q[b,k] * w_f[j,a,k]; both operands K-contiguous.
// Block tile: BM=64 b-rows x one full j (128 a-cols), K looped in chunks of 32.
// Epilogue reduces the 128 a-cols (weighted by w_h) down to v[b,j].
// grid = (4 b-tiles, 256 j), block = 256 threads.
// Thread tile: 8 b x 4 a  (ty = tid/32 -> b-group, tx = tid%32 -> a-group).
// ---------------------------------------------------------------------------
#define BM 64
#define BK 32

__global__ __launch_bounds__(256) void k1_gemm_tanh_reduce(
    const float* __restrict__ emb_q,   // [BSZ, D]
    const float* __restrict__ w_f,     // [D(j), DA(a), D(k)]
    const float* __restrict__ b_f,     // [D(j), DA(a)]
    const float* __restrict__ w_h)     // [DA]
{
    __shared__ float As[BK][BM];   // [k][b]
    __shared__ float Bs[BK][DA_];  // [k][a]

    const int j   = blockIdx.y;
    const int b0  = blockIdx.x * BM;
    const int tid = threadIdx.x;
    const int tx  = tid & 31;   // lane == a-group
    const int ty  = tid >> 5;   // warp == b-group (0..7)

    float acc[8][4];
    #pragma unroll
    for (int i = 0; i < 8; i++)
        #pragma unroll
        for (int q = 0; q < 4; q++) acc[i][q] = 0.f;

    const float* wj = w_f + (size_t)j * DA_ * D_;

    for (int kc = 0; kc < D_; kc += BK) {
        // Load A tile: 64 b x 32 k (2 float4 per thread), store transposed.
        #pragma unroll
        for (int it = 0; it < 2; it++) {
            int idx = tid + it * 256;          // 0..511
            int r = idx >> 3;                  // b row 0..63
            int c = (idx & 7) << 2;            // k col {0,4,...,28}
            float4 v4 = *reinterpret_cast<const float4*>(
                &emb_q[(size_t)(b0 + r) * D_ + kc + c]);
            As[c + 0][r] = v4.x; As[c + 1][r] = v4.y;
            As[c + 2][r] = v4.z; As[c + 3][r] = v4.w;
        }
        // Load B tile: 128 a x 32 k (4 float4 per thread), store transposed.
        #pragma unroll
        for (int it = 0; it < 4; it++) {
            int idx = tid + it * 256;          // 0..1023
            int r = idx >> 3;                  // a 0..127
            int c = (idx & 7) << 2;
            float4 v4 = *reinterpret_cast<const float4*>(
                &wj[(size_t)r * D_ + kc + c]);
            Bs[c + 0][r] = v4.x; Bs[c + 1][r] = v4.y;
            Bs[c + 2][r] = v4.z; Bs[c + 3][r] = v4.w;
        }
        __syncthreads();

        #pragma unroll
        for (int k = 0; k < BK; k++) {
            // a-frag: broadcast reads (whole warp same address)
            float4 a4l = *reinterpret_cast<const float4*>(&As[k][ty * 8]);
            float4 a4h = *reinterpret_cast<const float4*>(&As[k][ty * 8 + 4]);
            // b-frag: consecutive float4s across lanes -> conflict-free
            float4 b4  = *reinterpret_cast<const float4*>(&Bs[k][tx * 4]);
            float af[8] = {a4l.x, a4l.y, a4l.z, a4l.w, a4h.x, a4h.y, a4h.z, a4h.w};
            float bf[4] = {b4.x, b4.y, b4.z, b4.w};
            #pragma unroll
            for (int i = 0; i < 8; i++)
                #pragma unroll
                for (int q = 0; q < 4; q++)
                    acc[i][q] = fmaf(af[i], bf[q], acc[i][q]);
        }
        __syncthreads();
    }

    // Epilogue: tanh(acc + b_f) * w_h, reduce over the 4 local a's, then
    // across the 32 lanes (full 128 a's), write v[b][j].
    float4 bf4 = *reinterpret_cast<const float4*>(&b_f[(size_t)j * DA_ + tx * 4]);
    float4 wh4 = *reinterpret_cast<const float4*>(&w_h[tx * 4]);

    float part[8];
    #pragma unroll
    for (int i = 0; i < 8; i++) {
        float s;
        s  = tanhf(acc[i][0] + bf4.x) * wh4.x;
        s += tanhf(acc[i][1] + bf4.y) * wh4.y;
        s += tanhf(acc[i][2] + bf4.z) * wh4.z;
        s += tanhf(acc[i][3] + bf4.w) * wh4.w;
        part[i] = s;
    }
    #pragma unroll
    for (int off = 16; off > 0; off >>= 1)
        #pragma unroll
        for (int i = 0; i < 8; i++)
            part[i] += __shfl_down_sync(0xffffffffu, part[i], off);

    if (tx == 0) {
        #pragma unroll
        for (int i = 0; i < 8; i++)
            g_v[(size_t)(b0 + ty * 8 + i) * D_ + j] = part[i];
    }
}

// ---------------------------------------------------------------------------
// Kernel 2: out[b,l] = sum_j emb_iseq[b,l,j] * v[b,j]   (HBM-bound, 256 MB)
// One warp per l-row; lane holds v[lane*8 .. lane*8+7] in registers.
// grid = (256 b, 16 l-chunks), block = 256 threads (8 warps x 8 l each).
// ---------------------------------------------------------------------------
__global__ __launch_bounds__(256) void k2_gemv(
    const float* __restrict__ emb_iseq,  // [BSZ, MAXLEN, D]
    float* __restrict__ out)             // [BSZ, MAXLEN]
{
    const int b    = blockIdx.x;
    const int l0   = blockIdx.y * 64;
    const int lane = threadIdx.x & 31;
    const int w    = threadIdx.x >> 5;

    const float* vb = &g_v[(size_t)b * D_ + lane * 8];
    float4 v0 = *reinterpret_cast<const float4*>(vb);
    float4 v1 = *reinterpret_cast<const float4*>(vb + 4);

    const float* base = emb_iseq + (size_t)b * MAXLEN_ * D_;
    const int lbase = l0 + w * 8;

    #pragma unroll 4
    for (int li = 0; li < 8; li++) {
        int l = lbase + li;
        const float4* p = reinterpret_cast<const float4*>(
            &base[(size_t)l * D_ + lane * 8]);
        float4 e0 = p[0];
        float4 e1 = p[1];
        float s = e0.x * v0.x + e0.y * v0.y + e0.z * v0.z + e0.w * v0.w
                + e1.x * v1.x + e1.y * v1.y + e1.z * v1.z + e1.w * v1.w;
        #pragma unroll
        for (int off = 16; off > 0; off >>= 1)
            s += __shfl_down_sync(0xffffffffu, s, off);
        if (lane == 0) out[(size_t)b * MAXLEN_ + l] = s;
    }
}

extern "C" void kernel_launch(void* const* d_in, const int* in_sizes, int n_in,
                              void* d_out, int out_size) {
    const float* emb_q    = (const float*)d_in[0];  // [256, 256]
    const float* emb_iseq = (const float*)d_in[1];  // [256, 1024, 256]
    const float* w_f      = (const float*)d_in[2];  // [256, 128, 256]
    const float* b_f      = (const float*)d_in[3];  // [256, 128]
    const float* w_h      = (const float*)d_in[4];  // [128, 1]
    float* out = (float*)d_out;                     // [256, 1024]
    (void)in_sizes; (void)n_in; (void)out_size;

    dim3 g1(BSZ_ / BM, D_);   // (4, 256)
    k1_gemm_tanh_reduce<<<g1, 256>>>(emb_q, w_f, b_f, w_h);

    dim3 g2(BSZ_, MAXLEN_ / 64);  // (256, 16)
    k2_gemv<<<g2, 256>>>(emb_iseq, out);
}

// round 6
// speedup vs baseline: 1.0407x; 1.0407x over previous
#include <cuda_runtime.h>
#include <math.h>

#define D_      256
#define DA_     128
#define BSZ_    256
#define MAXLEN_ 1024

// Scratch: v[b][j] = sum_a tanh(trans_q[b,j,a] + b_f[j,a]) * w_h[a]
__device__ float g_v[BSZ_ * D_];

// ---- packed f32x2 helpers (ptxas never auto-fuses FFMA2; must come via PTX) ----
__device__ __forceinline__ unsigned long long pk2(float lo, float hi) {
    unsigned long long r;
    asm("mov.b64 %0, {%1, %2};" : "=l"(r) : "f"(lo), "f"(hi));
    return r;
}
__device__ __forceinline__ void upk2(unsigned long long v, float& lo, float& hi) {
    asm("mov.b64 {%0, %1}, %2;" : "=f"(lo), "=f"(hi) : "l"(v));
}
__device__ __forceinline__ void ffma2(unsigned long long& c,
                                      unsigned long long a,
                                      unsigned long long b) {
    asm("fma.rn.f32x2 %0, %1, %2, %3;" : "=l"(c) : "l"(a), "l"(b), "l"(c));
}

// ---------------------------------------------------------------------------
// Kernel 1: fused GEMM + tanh + weighted reduce over a, FFMA2 inner loop.
// Block tile: 128 b-rows x one full j (128 a-cols). BK=16.
// Threads 256 as (ty=tid>>4 -> 16 b-groups of 8, tx=tid&15 -> 16 a-groups of 8).
// Thread tile 8b x 8a; accumulators packed in f32x2 pairs along a.
// grid = (2 b-tiles, 256 j).
// ---------------------------------------------------------------------------
#define BM 128
#define BK 16

__global__ __launch_bounds__(256, 2) void k1_gemm_tanh_reduce(
    const float* __restrict__ emb_q,   // [BSZ, D]
    const float* __restrict__ w_f,     // [D(j), DA(a), D(k)]
    const float* __restrict__ b_f,     // [D(j), DA(a)]
    const float* __restrict__ w_h)     // [DA]
{
    __shared__ float As[BK][BM];   // [k][b]
    __shared__ float Bs[BK][DA_];  // [k][a]

    const int j   = blockIdx.y;
    const int b0  = blockIdx.x * BM;
    const int tid = threadIdx.x;
    const int tx  = tid & 15;   // a-group (cols tx*8 .. tx*8+7)
    const int ty  = tid >> 4;   // b-group (rows ty*8 .. ty*8+7)

    unsigned long long acc[8][4];
    #pragma unroll
    for (int i = 0; i < 8; i++)
        #pragma unroll
        for (int q = 0; q < 4; q++) acc[i][q] = 0ull;

    const float* wj = w_f + (size_t)j * DA_ * D_;

    for (int kc = 0; kc < D_; kc += BK) {
        // A tile: 128 b x 16 k = 512 float4; 2 per thread. Store transposed.
        #pragma unroll
        for (int it = 0; it < 2; it++) {
            int idx = tid + it * 256;          // 0..511
            int r = idx >> 2;                  // b row 0..127
            int c = (idx & 3) << 2;            // k col {0,4,8,12}
            float4 v4 = *reinterpret_cast<const float4*>(
                &emb_q[(size_t)(b0 + r) * D_ + kc + c]);
            As[c + 0][r] = v4.x; As[c + 1][r] = v4.y;
            As[c + 2][r] = v4.z; As[c + 3][r] = v4.w;
        }
        // B tile: 128 a x 16 k = 512 float4; 2 per thread. Store transposed.
        #pragma unroll
        for (int it = 0; it < 2; it++) {
            int idx = tid + it * 256;
            int r = idx >> 2;                  // a 0..127
            int c = (idx & 3) << 2;
            float4 v4 = *reinterpret_cast<const float4*>(
                &wj[(size_t)r * D_ + kc + c]);
            Bs[c + 0][r] = v4.x; Bs[c + 1][r] = v4.y;
            Bs[c + 2][r] = v4.z; Bs[c + 3][r] = v4.w;
        }
        __syncthreads();

        #pragma unroll
        for (int k = 0; k < BK; k++) {
            float4 a0 = *reinterpret_cast<const float4*>(&As[k][ty * 8]);
            float4 a1 = *reinterpret_cast<const float4*>(&As[k][ty * 8 + 4]);
            float4 bb0 = *reinterpret_cast<const float4*>(&Bs[k][tx * 8]);
            float4 bb1 = *reinterpret_cast<const float4*>(&Bs[k][tx * 8 + 4]);

            unsigned long long bd[4];
            bd[0] = pk2(bb0.x, bb0.y); bd[1] = pk2(bb0.z, bb0.w);
            bd[2] = pk2(bb1.x, bb1.y); bd[3] = pk2(bb1.z, bb1.w);

            float av[8] = {a0.x, a0.y, a0.z, a0.w, a1.x, a1.y, a1.z, a1.w};
            #pragma unroll
            for (int i = 0; i < 8; i++) {
                unsigned long long ad = pk2(av[i], av[i]);
                #pragma unroll
                for (int q = 0; q < 4; q++)
                    ffma2(acc[i][q], ad, bd[q]);
            }
        }
        __syncthreads();
    }

    // Epilogue: tanh(acc + b_f) * w_h over this thread's 8 a-cols, reduce
    // across the 16 tx-threads (shfl width 16), write v[b][j].
    float4 bf0 = *reinterpret_cast<const float4*>(&b_f[(size_t)j * DA_ + tx * 8]);
    float4 bf1 = *reinterpret_cast<const float4*>(&b_f[(size_t)j * DA_ + tx * 8 + 4]);
    float4 wh0 = *reinterpret_cast<const float4*>(&w_h[tx * 8]);
    float4 wh1 = *reinterpret_cast<const float4*>(&w_h[tx * 8 + 4]);
    float bfv[8] = {bf0.x, bf0.y, bf0.z, bf0.w, bf1.x, bf1.y, bf1.z, bf1.w};
    float whv[8] = {wh0.x, wh0.y, wh0.z, wh0.w, wh1.x, wh1.y, wh1.z, wh1.w};

    float part[8];
    #pragma unroll
    for (int i = 0; i < 8; i++) {
        float s = 0.f;
        #pragma unroll
        for (int q = 0; q < 4; q++) {
            float lo, hi;
            upk2(acc[i][q], lo, hi);
            s += tanhf(lo + bfv[q * 2 + 0]) * whv[q * 2 + 0];
            s += tanhf(hi + bfv[q * 2 + 1]) * whv[q * 2 + 1];
        }
        part[i] = s;
    }
    #pragma unroll
    for (int off = 8; off > 0; off >>= 1)
        #pragma unroll
        for (int i = 0; i < 8; i++)
            part[i] += __shfl_down_sync(0xffffffffu, part[i], off, 16);

    if (tx == 0) {
        #pragma unroll
        for (int i = 0; i < 8; i++)
            g_v[(size_t)(b0 + ty * 8 + i) * D_ + j] = part[i];
    }
}

// ---------------------------------------------------------------------------
// Kernel 2: out[b,l] = sum_j emb_iseq[b,l,j] * v[b,j]   (HBM-bound, 256 MB)
// One warp per l-row; lane holds v[lane*8 .. lane*8+7] in registers.
// Streaming loads (__ldcs) — emb_iseq is read exactly once.
// ---------------------------------------------------------------------------
__global__ __launch_bounds__(256) void k2_gemv(
    const float* __restrict__ emb_iseq,  // [BSZ, MAXLEN, D]
    float* __restrict__ out)             // [BSZ, MAXLEN]
{
    const int b    = blockIdx.x;
    const int l0   = blockIdx.y * 64;
    const int lane = threadIdx.x & 31;
    const int w    = threadIdx.x >> 5;

    const float* vb = &g_v[(size_t)b * D_ + lane * 8];
    float4 v0 = *reinterpret_cast<const float4*>(vb);
    float4 v1 = *reinterpret_cast<const float4*>(vb + 4);

    const float* base = emb_iseq + (size_t)b * MAXLEN_ * D_;
    const int lbase = l0 + w * 8;

    #pragma unroll 4
    for (int li = 0; li < 8; li++) {
        int l = lbase + li;
        const float4* p = reinterpret_cast<const float4*>(
            &base[(size_t)l * D_ + lane * 8]);
        float4 e0 = __ldcs(p);
        float4 e1 = __ldcs(p + 1);
        float s = e0.x * v0.x + e0.y * v0.y + e0.z * v0.z + e0.w * v0.w
                + e1.x * v1.x + e1.y * v1.y + e1.z * v1.z + e1.w * v1.w;
        #pragma unroll
        for (int off = 16; off > 0; off >>= 1)
            s += __shfl_down_sync(0xffffffffu, s, off);
        if (lane == 0) out[(size_t)b * MAXLEN_ + l] = s;
    }
}

extern "C" void kernel_launch(void* const* d_in, const int* in_sizes, int n_in,
                              void* d_out, int out_size) {
    const float* emb_q    = (const float*)d_in[0];  // [256, 256]
    const float* emb_iseq = (const float*)d_in[1];  // [256, 1024, 256]
    const float* w_f      = (const float*)d_in[2];  // [256, 128, 256]
    const float* b_f      = (const float*)d_in[3];  // [256, 128]
    const float* w_h      = (const float*)d_in[4];  // [128, 1]
    float* out = (float*)d_out;                     // [256, 1024]
    (void)in_sizes; (void)n_in; (void)out_size;

    dim3 g1(BSZ_ / BM, D_);   // (2, 256)
    k1_gemm_tanh_reduce<<<g1, 256>>>(emb_q, w_f, b_f, w_h);

    dim3 g2(BSZ_, MAXLEN_ / 64);  // (256, 16)
    k2_gemv<<<g2, 256>>>(emb_iseq, out);
}